// round 4
// baseline (speedup 1.0000x reference)
#include <cuda_runtime.h>
#include <math.h>
#include <stdint.h>

#define BN 2
#define TT 8
#define NN 10000
#define FF 128
#define EE 320000
#define ENE (EE+NN)
#define LL 2
#define KD 128
#define G3 384

__device__ int   g_src[EE];
__device__ int   g_tgt[EE];
__device__ float g_deg[NN];
__device__ float g_dinv[NN];
__device__ int   g_cnt[NN];
__device__ int   g_colptr[NN+1];
__device__ int   g_erow[ENE];
__device__ float g_ewn[ENE];
__device__ float g_W[BN*LL*FF*KD];     // [b][c][k(din)][i(dout)]
__device__ float g_buf1[BN*NN*KD];     // layer-0 output
__device__ float g_obuf[BN*NN*KD];     // GEMM result
__device__ float g_scores[BN*NN];
__device__ float g_pooled[BN*KD*FF];   // [b][i(dout)][k(din)]
__device__ float g_wT[LL*2*FF*G3];     // [c][m][k][j]
__device__ float g_G[2*BN*KD*G3];      // [m][b][i][j]

__global__ void k_convert(const void* __restrict__ ei){
  const long long* q = (const long long*)ei;
  bool is64 = true;
  #pragma unroll
  for(int j=0;j<8;j++){ long long v = q[j]; if(v < 0 || v >= NN) is64 = false; }
  int e = blockIdx.x*blockDim.x + threadIdx.x;
  if(e < EE){
    if(is64){ g_src[e] = (int)q[e]; g_tgt[e] = (int)q[EE+e]; }
    else { const int* pi = (const int*)ei; g_src[e] = pi[e]; g_tgt[e] = pi[EE+e]; }
  }
}

__global__ void k_init(const float* __restrict__ W0, const float* __restrict__ wih,
                       const float* __restrict__ whh){
  int i = blockIdx.x*blockDim.x + threadIdx.x;
  if(i < NN){ g_deg[i]=0.f; g_cnt[i]=0; }
  if(i < BN*LL*FF*KD){ g_W[i] = W0[i & (LL*FF*KD - 1)]; }
  if(i < LL*2*FF*G3){
    int j = i % G3; int t2 = i / G3; int k = t2 % FF; int t3 = t2 / FF;
    int m = t3 & 1; int cc = t3 >> 1;
    const float* src = m ? whh : wih;
    g_wT[i] = src[((size_t)cc*G3 + j)*FF + k];
  }
}

__global__ void k_degcnt(const float* __restrict__ ew){
  int e = blockIdx.x*blockDim.x + threadIdx.x;
  if(e >= ENE) return;
  int col; float w;
  if(e < EE){ col = g_tgt[e]; w = ew[e]; } else { col = e - EE; w = 1.f; }
  atomicAdd(&g_deg[col], w);
  atomicAdd(&g_cnt[col], 1);
}

__global__ void k_dinv(){
  int i = blockIdx.x*blockDim.x + threadIdx.x;
  if(i < NN){ float d = g_deg[i]; g_dinv[i] = d > 0.f ? rsqrtf(d) : 0.f; }
}

__global__ void k_scan(){
  __shared__ int part[1024];
  int tid = threadIdx.x;
  const int CH = 10;
  int base = tid*CH;
  int loc[CH]; int s = 0;
  #pragma unroll
  for(int i=0;i<CH;i++){ int idx = base+i; int v = (idx<NN)?g_cnt[idx]:0; loc[i]=s; s+=v; }
  part[tid]=s; __syncthreads();
  for(int off=1; off<1024; off<<=1){
    int v = part[tid];
    int add = (tid>=off)? part[tid-off] : 0;
    __syncthreads();
    part[tid] = v+add;
    __syncthreads();
  }
  int excl = (tid>0)? part[tid-1] : 0;
  #pragma unroll
  for(int i=0;i<CH;i++){ int idx = base+i; if(idx<NN) g_colptr[idx]=excl+loc[i]; }
  if(tid==1023) g_colptr[NN]=part[1023];
  for(int idx=tid; idx<NN; idx+=1024) g_cnt[idx]=0;
}

__global__ void k_fill(const float* __restrict__ ew){
  int e = blockIdx.x*blockDim.x + threadIdx.x;
  if(e >= ENE) return;
  int col, r; float w;
  if(e < EE){ col = g_tgt[e]; r = g_src[e]; w = ew[e]; }
  else { col = e - EE; r = col; w = 1.f; }
  int pos = g_colptr[col] + atomicAdd(&g_cnt[col], 1);
  g_erow[pos] = r;
  g_ewn[pos] = g_dinv[r]*w*g_dinv[col];
}

__global__ void k_scores(const float* __restrict__ in, size_t bstride,
                         const float* __restrict__ p, int c){
  int gw = (blockIdx.x*blockDim.x + threadIdx.x) >> 5;
  int lane = threadIdx.x & 31;
  if(gw >= BN*NN) return;
  int b = gw / NN, n = gw - b*NN;
  const float* base = in ? in : g_buf1;
  const float4* row = (const float4*)(base + (size_t)b*bstride + (size_t)n*FF);
  float4 xv = row[lane];
  float4 pv = ((const float4*)(p + c*FF))[lane];
  float acc = xv.x*pv.x + xv.y*pv.y + xv.z*pv.z + xv.w*pv.w;
  #pragma unroll
  for(int o=16;o;o>>=1) acc += __shfl_xor_sync(0xFFFFFFFFu, acc, o);
  if(lane==0) g_scores[b*NN+n]=acc;
}

__global__ void k_topk(const float* __restrict__ in, size_t bstride,
                       const float* __restrict__ p, int c){
  __shared__ unsigned skey[NN];
  __shared__ unsigned hist[256];
  __shared__ unsigned long long cand[256];
  __shared__ int sidx[128];
  __shared__ float sscale[128];
  __shared__ float s_pn;
  __shared__ unsigned s_pref;
  __shared__ int s_need, s_cnt;
  int tid = threadIdx.x, b = blockIdx.x;
  if(tid==0){ s_pn=0.f; s_cnt=0; s_need=128; s_pref=0; }
  __syncthreads();
  if(tid < FF){ float pv = p[c*FF+tid]; atomicAdd(&s_pn, pv*pv); }
  for(int n=tid; n<NN; n+=1024){
    float s = g_scores[b*NN+n];
    unsigned u = __float_as_uint(s);
    u ^= (u>>31) ? 0xFFFFFFFFu : 0x80000000u;
    skey[n] = u;
  }
  __syncthreads();
  float pnorm = sqrtf(s_pn);
  for(int r=0;r<4;r++){
    int shift = 24-8*r;
    for(int i=tid;i<256;i+=1024) hist[i]=0;
    __syncthreads();
    unsigned pref = s_pref;
    for(int n=tid;n<NN;n+=1024){
      unsigned k = skey[n];
      bool ok = (r==0) || ((k >> (shift+8)) == pref);
      if(ok) atomicAdd(&hist[(k>>shift)&255],1);
    }
    __syncthreads();
    if(tid==0){
      int need = s_need; int cum = 0;
      for(int bb=255; bb>=0; bb--){
        int h = (int)hist[bb];
        if(cum + h >= need){ s_need = need - cum; s_pref = (pref<<8)|(unsigned)bb; break; }
        cum += h;
      }
    }
    __syncthreads();
  }
  unsigned kth = s_pref;
  for(int i=tid;i<256;i+=1024) cand[i]=0xFFFFFFFFFFFFFFFFull;
  __syncthreads();
  for(int n=tid;n<NN;n+=1024){
    unsigned k = skey[n];
    if(k >= kth){
      int pos = atomicAdd(&s_cnt,1);
      if(pos < 256){
        unsigned long long comp = ((unsigned long long)k<<32) | (unsigned)(~n);
        cand[pos] = ~comp;   // ascending sort of ~comp == descending (key, idx-asc)
      }
    }
  }
  __syncthreads();
  for(int kk=2; kk<=256; kk<<=1){
    for(int j=kk>>1; j>0; j>>=1){
      if(tid < 256){
        int ixj = tid ^ j;
        if(ixj > tid){
          bool up = ((tid & kk) == 0);
          unsigned long long a = cand[tid], b2 = cand[ixj];
          if((a > b2) == up){ cand[tid]=b2; cand[ixj]=a; }
        }
      }
      __syncthreads();
    }
  }
  if(tid < 128){
    unsigned long long comp = ~cand[tid];
    unsigned k = (unsigned)(comp>>32);
    int idx = (int)(~(unsigned)comp);
    unsigned u = (k & 0x80000000u) ? (k ^ 0x80000000u) : ~k;
    float val = __uint_as_float(u) / pnorm;
    sidx[tid] = idx;
    sscale[tid] = tanhf(val);
  }
  __syncthreads();
  const float* base = in ? in : g_buf1;
  for(int e2=tid; e2<KD*FF; e2+=1024){
    int i = e2 >> 7, d = e2 & 127;
    g_pooled[((size_t)b*KD+i)*FF+d] =
        base[(size_t)b*bstride + (size_t)sidx[i]*FF + d]*sscale[i];
  }
}

__global__ void k_grumm(int c, const float* __restrict__ bih, const float* __restrict__ bhh){
  __shared__ float sa[FF][16];
  int m = blockIdx.z & 1, b = blockIdx.z >> 1;
  int tid = threadIdx.x;
  int j = blockIdx.x*192 + tid;
  int i0 = blockIdx.y*16;
  for(int idx=tid; idx<16*FF; idx+=192){
    int ii = idx & 15, k = idx >> 4;
    float v;
    if(m==0) v = g_pooled[((size_t)b*KD + i0+ii)*FF + k];
    else     v = g_W[(((size_t)b*LL + c)*FF + k)*KD + (i0+ii)];
    sa[k][ii] = v;
  }
  __syncthreads();
  const float* wrow = &g_wT[(size_t)(c*2+m)*FF*G3 + j];
  float acc[16];
  #pragma unroll
  for(int ii=0;ii<16;ii++) acc[ii]=0.f;
  #pragma unroll 2
  for(int k=0;k<FF;k++){
    float wv = wrow[(size_t)k*G3];
    const float4* sr = (const float4*)&sa[k][0];
    float4 a0=sr[0], a1=sr[1], a2=sr[2], a3=sr[3];
    acc[0] +=a0.x*wv; acc[1] +=a0.y*wv; acc[2] +=a0.z*wv; acc[3] +=a0.w*wv;
    acc[4] +=a1.x*wv; acc[5] +=a1.y*wv; acc[6] +=a1.z*wv; acc[7] +=a1.w*wv;
    acc[8] +=a2.x*wv; acc[9] +=a2.y*wv; acc[10]+=a2.z*wv; acc[11]+=a2.w*wv;
    acc[12]+=a3.x*wv; acc[13]+=a3.y*wv; acc[14]+=a3.z*wv; acc[15]+=a3.w*wv;
  }
  float bb = (m==0 ? bih : bhh)[c*G3 + j];
  #pragma unroll
  for(int ii=0;ii<16;ii++)
    g_G[(((size_t)m*BN + b)*KD + (i0+ii))*G3 + j] = acc[ii] + bb;
}

__global__ void k_grugate(int c){
  int id = blockIdx.x*blockDim.x + threadIdx.x;
  if(id >= BN*KD*FF) return;
  int b = id / (KD*FF);
  int rem = id - b*KD*FF;
  int i = rem >> 7;
  int j = rem & 127;
  size_t gib = (((size_t)0*BN + b)*KD + i)*G3 + j;
  size_t ghb = (((size_t)1*BN + b)*KD + i)*G3 + j;
  float gir=g_G[gib], giz=g_G[gib+128], gin=g_G[gib+256];
  float ghr=g_G[ghb], ghz=g_G[ghb+128], ghn=g_G[ghb+256];
  float r = 1.f/(1.f+expf(-(gir+ghr)));
  float z = 1.f/(1.f+expf(-(giz+ghz)));
  float nn2 = tanhf(gin + r*ghn);
  float* Wp = &g_W[(((size_t)b*LL + c)*FF + j)*KD + i];
  float h = *Wp;
  *Wp = (1.f - z)*nn2 + z*h;
}

__global__ void k_gemm(const float* __restrict__ in, size_t bstride, int c){
  __shared__ float Ash[FF][64];   // [k][n] 32KB
  __shared__ float Wsh[32][KD];   // k-chunk 16KB
  int b = blockIdx.y;
  int n0 = blockIdx.x*64;
  int tid = threadIdx.x;
  const float* base = in ? in : g_buf1;
  {
    int n = tid & 63, kq = tid >> 6;
    const float* arow = base + (size_t)b*bstride + (size_t)(n0+n)*FF + kq*32;
    bool valid = (n0+n) < NN;
    #pragma unroll
    for(int f=0; f<8; f++){
      float4 v = valid ? *(const float4*)(arow + f*4) : make_float4(0.f,0.f,0.f,0.f);
      int k = kq*32 + f*4;
      Ash[k][n]=v.x; Ash[k+1][n]=v.y; Ash[k+2][n]=v.z; Ash[k+3][n]=v.w;
    }
  }
  int tx = tid & 31, ty = tid >> 5;
  int jb = tx*4, nb = ty*8;
  float acc[8][4];
  #pragma unroll
  for(int i=0;i<8;i++){ acc[i][0]=0.f; acc[i][1]=0.f; acc[i][2]=0.f; acc[i][3]=0.f; }
  const float4* Wg = (const float4*)&g_W[(size_t)(b*LL+c)*FF*KD];
  for(int kc=0; kc<4; kc++){
    __syncthreads();
    float4* W4 = (float4*)Wsh;
    #pragma unroll
    for(int i=0;i<4;i++) W4[tid + i*256] = Wg[kc*1024 + tid + i*256];
    __syncthreads();
    #pragma unroll 4
    for(int kk=0;kk<32;kk++){
      int k = kc*32 + kk;
      float4 wv = *(float4*)&Wsh[kk][jb];
      float4 a0 = *(float4*)&Ash[k][nb];
      float4 a1 = *(float4*)&Ash[k][nb+4];
      acc[0][0]+=a0.x*wv.x; acc[0][1]+=a0.x*wv.y; acc[0][2]+=a0.x*wv.z; acc[0][3]+=a0.x*wv.w;
      acc[1][0]+=a0.y*wv.x; acc[1][1]+=a0.y*wv.y; acc[1][2]+=a0.y*wv.z; acc[1][3]+=a0.y*wv.w;
      acc[2][0]+=a0.z*wv.x; acc[2][1]+=a0.z*wv.y; acc[2][2]+=a0.z*wv.z; acc[2][3]+=a0.z*wv.w;
      acc[3][0]+=a0.w*wv.x; acc[3][1]+=a0.w*wv.y; acc[3][2]+=a0.w*wv.z; acc[3][3]+=a0.w*wv.w;
      acc[4][0]+=a1.x*wv.x; acc[4][1]+=a1.x*wv.y; acc[4][2]+=a1.x*wv.z; acc[4][3]+=a1.x*wv.w;
      acc[5][0]+=a1.y*wv.x; acc[5][1]+=a1.y*wv.y; acc[5][2]+=a1.y*wv.z; acc[5][3]+=a1.y*wv.w;
      acc[6][0]+=a1.z*wv.x; acc[6][1]+=a1.z*wv.y; acc[6][2]+=a1.z*wv.z; acc[6][3]+=a1.z*wv.w;
      acc[7][0]+=a1.w*wv.x; acc[7][1]+=a1.w*wv.y; acc[7][2]+=a1.w*wv.z; acc[7][3]+=a1.w*wv.w;
    }
  }
  #pragma unroll
  for(int i=0;i<8;i++){
    int row = n0 + nb + i;
    if(row < NN){
      *(float4*)&g_obuf[((size_t)b*NN + row)*KD + jb] =
          make_float4(acc[i][0],acc[i][1],acc[i][2],acc[i][3]);
    }
  }
}

__global__ void k_agg(int c, const float* __restrict__ bias, float* __restrict__ out){
  int gw = (blockIdx.x*blockDim.x + threadIdx.x) >> 5;
  int lane = threadIdx.x & 31;
  if(gw >= BN*NN) return;
  int b = gw / NN, v = gw - b*NN;
  int beg = g_colptr[v], end = g_colptr[v+1];
  const float* ob = g_obuf + (size_t)b*NN*KD + lane*4;
  float ax=0.f, ay=0.f, az=0.f, aw=0.f;
  int j = beg;
  for(; j+3 < end; j+=4){
    int r0=g_erow[j], r1=g_erow[j+1], r2=g_erow[j+2], r3=g_erow[j+3];
    float w0=g_ewn[j], w1=g_ewn[j+1], w2=g_ewn[j+2], w3=g_ewn[j+3];
    float4 o0=*(const float4*)(ob + (size_t)r0*KD);
    float4 o1=*(const float4*)(ob + (size_t)r1*KD);
    float4 o2=*(const float4*)(ob + (size_t)r2*KD);
    float4 o3=*(const float4*)(ob + (size_t)r3*KD);
    ax += w0*o0.x + w1*o1.x + w2*o2.x + w3*o3.x;
    ay += w0*o0.y + w1*o1.y + w2*o2.y + w3*o3.y;
    az += w0*o0.z + w1*o1.z + w2*o2.z + w3*o3.z;
    aw += w0*o0.w + w1*o1.w + w2*o2.w + w3*o3.w;
  }
  for(; j<end; j++){
    int r0=g_erow[j]; float w0=g_ewn[j];
    float4 o0=*(const float4*)(ob + (size_t)r0*KD);
    ax += w0*o0.x; ay += w0*o0.y; az += w0*o0.z; aw += w0*o0.w;
  }
  float4 bv = *(const float4*)(bias + c*KD + lane*4);
  float4 res;
  res.x = fmaxf(ax+bv.x, 0.f);
  res.y = fmaxf(ay+bv.y, 0.f);
  res.z = fmaxf(az+bv.z, 0.f);
  res.w = fmaxf(aw+bv.w, 0.f);
  float* dst = out ? out : g_buf1;
  *(float4*)(dst + ((size_t)b*NN + v)*KD + lane*4) = res;
}

extern "C" void kernel_launch(void* const* d_in, const int* in_sizes, int n_in,
                              void* d_out, int out_size){
  const float* x    = (const float*)d_in[0];
  const void*  ei   = d_in[1];
  const float* ew   = (const float*)d_in[2];
  const float* W0   = (const float*)d_in[3];
  const float* p    = (const float*)d_in[4];
  const float* wih  = (const float*)d_in[5];
  const float* whh  = (const float*)d_in[6];
  const float* bih  = (const float*)d_in[7];
  const float* bhh  = (const float*)d_in[8];
  const float* bias = (const float*)d_in[9];
  float* out = (float*)d_out;

  k_convert<<<(EE+255)/256,256>>>(ei);
  k_init<<<768,256>>>(W0, wih, whh);
  k_degcnt<<<(ENE+255)/256,256>>>(ew);
  k_dinv<<<(NN+255)/256,256>>>();
  k_scan<<<1,1024>>>();
  k_fill<<<(ENE+255)/256,256>>>(ew);

  const size_t xbs = (size_t)TT*NN*FF;
  const size_t bbs = (size_t)NN*FF;
  const int wgrid = (BN*NN*32+255)/256;
  for(int t=0;t<TT;t++){
    const float* xt = x + (size_t)t*NN*FF;
    // layer 0: pool -> evolve W -> GEMM -> propagate (needed every step)
    k_scores<<<wgrid,256>>>(xt, xbs, p, 0);
    k_topk<<<BN,1024>>>(xt, xbs, p, 0);
    k_grumm<<<dim3(2,8,2*BN),192>>>(0, bih, bhh);
    k_grugate<<<(BN*KD*FF+255)/256,256>>>(0);
    k_gemm<<<dim3((NN+63)/64,BN),256>>>(xt, xbs, 0);
    k_agg<<<wgrid,256>>>(0, bias, nullptr);
    // layer 1: pool -> evolve W every step; GEMM+propagate only at final step
    k_scores<<<wgrid,256>>>(nullptr, bbs, p, 1);
    k_topk<<<BN,1024>>>(nullptr, bbs, p, 1);
    k_grumm<<<dim3(2,8,2*BN),192>>>(1, bih, bhh);
    k_grugate<<<(BN*KD*FF+255)/256,256>>>(1);
    if(t==TT-1){
      k_gemm<<<dim3((NN+63)/64,BN),256>>>(nullptr, bbs, 1);
      k_agg<<<wgrid,256>>>(1, bias, out);
    }
  }
}

// round 8
// speedup vs baseline: 1.0908x; 1.0908x over previous
#include <cuda_runtime.h>
#include <math.h>
#include <stdint.h>

#define BN 2
#define TT 8
#define NN 10000
#define FF 128
#define EE 320000
#define ENE (EE+NN)
#define LL 2
#define KD 128
#define G3 384

__device__ int   g_src[EE];
__device__ int   g_tgt[EE];
__device__ float g_deg[NN];
__device__ float g_dinv[NN];
__device__ int   g_cnt[NN];
__device__ int   g_colptr[NN+1];
__device__ int   g_erow[ENE];
__device__ float g_ewn[ENE];
__device__ float g_W[BN*LL*FF*KD];     // [b][c][k(din)][i(dout)]
__device__ float g_buf1[BN*NN*KD];     // layer-0 output
__device__ float g_obuf[BN*NN*KD];     // GEMM result
__device__ float g_scores[BN*NN];
__device__ float g_pooled[BN*KD*FF];   // [b][i(dout)][k(din)]
__device__ float g_wT[LL*2*FF*G3];     // [c][m][k][j]

__global__ void k_convert(const void* __restrict__ ei){
  const long long* q = (const long long*)ei;
  bool is64 = true;
  #pragma unroll
  for(int j=0;j<8;j++){ long long v = q[j]; if(v < 0 || v >= NN) is64 = false; }
  int e = blockIdx.x*blockDim.x + threadIdx.x;
  if(e < EE){
    if(is64){ g_src[e] = (int)q[e]; g_tgt[e] = (int)q[EE+e]; }
    else { const int* pi = (const int*)ei; g_src[e] = pi[e]; g_tgt[e] = pi[EE+e]; }
  }
}

__global__ void k_init(const float* __restrict__ W0, const float* __restrict__ wih,
                       const float* __restrict__ whh){
  int i = blockIdx.x*blockDim.x + threadIdx.x;
  if(i < NN){ g_deg[i]=0.f; g_cnt[i]=0; }
  if(i < BN*LL*FF*KD){ g_W[i] = W0[i & (LL*FF*KD - 1)]; }
  if(i < LL*2*FF*G3){
    int j = i % G3; int t2 = i / G3; int k = t2 % FF; int t3 = t2 / FF;
    int m = t3 & 1; int cc = t3 >> 1;
    const float* src = m ? whh : wih;
    g_wT[i] = src[((size_t)cc*G3 + j)*FF + k];
  }
}

__global__ void k_degcnt(const float* __restrict__ ew){
  int e = blockIdx.x*blockDim.x + threadIdx.x;
  if(e >= ENE) return;
  int col; float w;
  if(e < EE){ col = g_tgt[e]; w = ew[e]; } else { col = e - EE; w = 1.f; }
  atomicAdd(&g_deg[col], w);
  atomicAdd(&g_cnt[col], 1);
}

__global__ void k_dinv(){
  int i = blockIdx.x*blockDim.x + threadIdx.x;
  if(i < NN){ float d = g_deg[i]; g_dinv[i] = d > 0.f ? rsqrtf(d) : 0.f; }
}

__global__ void k_scan(){
  __shared__ int part[1024];
  int tid = threadIdx.x;
  const int CH = 10;
  int base = tid*CH;
  int loc[CH]; int s = 0;
  #pragma unroll
  for(int i=0;i<CH;i++){ int idx = base+i; int v = (idx<NN)?g_cnt[idx]:0; loc[i]=s; s+=v; }
  part[tid]=s; __syncthreads();
  for(int off=1; off<1024; off<<=1){
    int v = part[tid];
    int add = (tid>=off)? part[tid-off] : 0;
    __syncthreads();
    part[tid] = v+add;
    __syncthreads();
  }
  int excl = (tid>0)? part[tid-1] : 0;
  #pragma unroll
  for(int i=0;i<CH;i++){ int idx = base+i; if(idx<NN) g_colptr[idx]=excl+loc[i]; }
  if(tid==1023) g_colptr[NN]=part[1023];
  for(int idx=tid; idx<NN; idx+=1024) g_cnt[idx]=0;
}

__global__ void k_fill(const float* __restrict__ ew){
  int e = blockIdx.x*blockDim.x + threadIdx.x;
  if(e >= ENE) return;
  int col, r; float w;
  if(e < EE){ col = g_tgt[e]; r = g_src[e]; w = ew[e]; }
  else { col = e - EE; r = col; w = 1.f; }
  int pos = g_colptr[col] + atomicAdd(&g_cnt[col], 1);
  g_erow[pos] = r;
  g_ewn[pos] = g_dinv[r]*w*g_dinv[col];
}

// scores for layer 0 (reads x_t)
__global__ void k_scores(const float* __restrict__ in, size_t bstride,
                         const float* __restrict__ p, int c){
  int gw = (blockIdx.x*blockDim.x + threadIdx.x) >> 5;
  int lane = threadIdx.x & 31;
  if(gw >= BN*NN) return;
  int b = gw / NN, n = gw - b*NN;
  const float4* row = (const float4*)(in + (size_t)b*bstride + (size_t)n*FF);
  float4 xv = row[lane];
  float4 pv = ((const float4*)(p + c*FF))[lane];
  float acc = xv.x*pv.x + xv.y*pv.y + xv.z*pv.z + xv.w*pv.w;
  #pragma unroll
  for(int o=16;o;o>>=1) acc += __shfl_xor_sync(0xFFFFFFFFu, acc, o);
  if(lane==0) g_scores[b*NN+n]=acc;
}

__global__ void k_topk(const float* __restrict__ in, size_t bstride,
                       const float* __restrict__ p, int c){
  __shared__ unsigned skey[NN];
  __shared__ int hist[256];
  __shared__ unsigned long long cand[256];
  __shared__ int sidx[128];
  __shared__ float sscale[128];
  __shared__ float s_pn;
  __shared__ unsigned s_pref;
  __shared__ int s_need, s_cnt;
  int tid = threadIdx.x, b = blockIdx.x;
  if(tid==0){ s_pn=0.f; s_cnt=0; s_need=128; s_pref=0; }
  __syncthreads();
  if(tid < FF){ float pv = p[c*FF+tid]; atomicAdd(&s_pn, pv*pv); }
  for(int n=tid; n<NN; n+=1024){
    float s = g_scores[b*NN+n];
    unsigned u = __float_as_uint(s);
    u ^= (u>>31) ? 0xFFFFFFFFu : 0x80000000u;
    skey[n] = u;
  }
  if(tid < 256) hist[tid]=0;
  __syncthreads();
  float pnorm = sqrtf(s_pn);
  for(int r=0;r<4;r++){
    int shift = 24-8*r;
    unsigned pref = s_pref;
    int need = s_need;
    for(int n=tid;n<NN;n+=1024){
      unsigned k = skey[n];
      bool ok = (r==0) || ((k >> (shift+8)) == pref);
      if(ok) atomicAdd(&hist[(k>>shift)&255],1);
    }
    __syncthreads();
    // warp 0: parallel suffix selection over descending buckets
    if(tid < 32){
      int vals[8], loc[8]; int s = 0;
      #pragma unroll
      for(int u=0;u<8;u++){ int v = hist[255-(tid*8+u)]; loc[u]=s; vals[u]=v; s+=v; }
      int t = s;
      #pragma unroll
      for(int off=1; off<32; off<<=1){
        int n3 = __shfl_up_sync(0xFFFFFFFFu, t, off);
        if(tid >= off) t += n3;
      }
      int lane_excl = t - s;
      #pragma unroll
      for(int u=0;u<8;u++){
        int excl = lane_excl + loc[u];
        int incl = excl + vals[u];
        if(excl < need && incl >= need){
          s_need = need - excl;
          s_pref = (pref<<8)|(unsigned)(255-(tid*8+u));
        }
      }
    }
    __syncthreads();
    if(r<3 && tid<256) hist[tid]=0;
    __syncthreads();
  }
  unsigned kth = s_pref;
  for(int i=tid;i<256;i+=1024) cand[i]=0xFFFFFFFFFFFFFFFFull;
  __syncthreads();
  for(int n=tid;n<NN;n+=1024){
    unsigned k = skey[n];
    if(k >= kth){
      int pos = atomicAdd(&s_cnt,1);
      if(pos < 256){
        unsigned long long comp = ((unsigned long long)k<<32) | (unsigned)(~n);
        cand[pos] = ~comp;   // ascending sort of ~comp == descending (key, idx-asc)
      }
    }
  }
  __syncthreads();
  for(int kk=2; kk<=256; kk<<=1){
    for(int j=kk>>1; j>0; j>>=1){
      if(tid < 256){
        int ixj = tid ^ j;
        if(ixj > tid){
          bool up = ((tid & kk) == 0);
          unsigned long long a = cand[tid], b2 = cand[ixj];
          if((a > b2) == up){ cand[tid]=b2; cand[ixj]=a; }
        }
      }
      __syncthreads();
    }
  }
  if(tid < 128){
    unsigned long long comp = ~cand[tid];
    unsigned k = (unsigned)(comp>>32);
    int idx = (int)(~(unsigned)comp);
    unsigned u = (k & 0x80000000u) ? (k ^ 0x80000000u) : ~k;
    float val = __uint_as_float(u) / pnorm;
    sidx[tid] = idx;
    sscale[tid] = tanhf(val);
  }
  __syncthreads();
  const float* base = in ? in : g_buf1;
  for(int e2=tid; e2<KD*FF; e2+=1024){
    int i = e2 >> 7, d = e2 & 127;
    g_pooled[((size_t)b*KD+i)*FF+d] =
        base[(size_t)b*bstride + (size_t)sidx[i]*FF + d]*sscale[i];
  }
}

// fused GRU: both gate GEMMs + gating + W update in one kernel
__global__ void k_gru(int c, const float* __restrict__ bih, const float* __restrict__ bhh){
  __shared__ float sa0[FF][16];     // pooled slice [k][ii]
  __shared__ float sa1[FF][16];     // W slice     [k][ii]
  __shared__ float sg[16][G3];      // j<256: gi+gh ; j>=256: gin
  __shared__ float sghn[16][128];   // ghn
  int b = blockIdx.y;
  int i0 = blockIdx.x*16;
  int tid = threadIdx.x;            // 384
  for(int idx=tid; idx<16*FF; idx+=384){
    int ii = idx & 15, k = idx >> 4;
    sa0[k][ii] = g_pooled[((size_t)b*KD + i0+ii)*FF + k];
    sa1[k][ii] = g_W[(((size_t)b*LL + c)*FF + k)*KD + (i0+ii)];
  }
  __syncthreads();
  int j = tid;
  const float* w0row = &g_wT[(size_t)(c*2+0)*FF*G3 + j];
  const float* w1row = &g_wT[(size_t)(c*2+1)*FF*G3 + j];
  float acc0[16], acc1[16];
  #pragma unroll
  for(int ii=0;ii<16;ii++){ acc0[ii]=0.f; acc1[ii]=0.f; }
  #pragma unroll 4
  for(int k=0;k<FF;k++){
    float w0 = w0row[(size_t)k*G3];
    float w1 = w1row[(size_t)k*G3];
    const float4* s0 = (const float4*)&sa0[k][0];
    const float4* s1 = (const float4*)&sa1[k][0];
    #pragma unroll
    for(int q=0;q<4;q++){
      float4 a = s0[q]; float4 h = s1[q];
      acc0[q*4+0]+=a.x*w0; acc0[q*4+1]+=a.y*w0; acc0[q*4+2]+=a.z*w0; acc0[q*4+3]+=a.w*w0;
      acc1[q*4+0]+=h.x*w1; acc1[q*4+1]+=h.y*w1; acc1[q*4+2]+=h.z*w1; acc1[q*4+3]+=h.w*w1;
    }
  }
  float bi = bih[c*G3+j], bh = bhh[c*G3+j];
  if(j < 256){
    #pragma unroll
    for(int ii=0;ii<16;ii++) sg[ii][j] = acc0[ii]+bi + acc1[ii]+bh;
  } else {
    #pragma unroll
    for(int ii=0;ii<16;ii++){ sg[ii][j] = acc0[ii]+bi; sghn[ii][j-256] = acc1[ii]+bh; }
  }
  __syncthreads();
  for(int idx=tid; idx<16*128; idx+=384){
    int ii = idx >> 7, jj = idx & 127;
    float r = 1.f/(1.f+expf(-sg[ii][jj]));
    float z = 1.f/(1.f+expf(-sg[ii][jj+128]));
    float n2 = tanhf(sg[ii][jj+256] + r*sghn[ii][jj]);
    float h = sa1[jj][ii];
    g_W[(((size_t)b*LL+c)*FF + jj)*KD + (i0+ii)] = (1.f-z)*n2 + z*h;
  }
}

// 128x128 tile GEMM, 8x8 micro-tile
__global__ void k_gemm(const float* __restrict__ in, size_t bstride, int c){
  __shared__ float Ash[32][132];
  __shared__ float Wsh[32][128];
  int b = blockIdx.y;
  int n0 = blockIdx.x*128;
  int tid = threadIdx.x;              // 256
  const float* base = in ? in : g_buf1;
  const float* Wg = &g_W[(size_t)(b*LL+c)*FF*KD];
  int tx = tid & 15, ty = tid >> 4;
  int jb = tx*8, nb = ty*8;
  float acc[8][8];
  #pragma unroll
  for(int u=0;u<8;u++)
    #pragma unroll
    for(int v=0;v<8;v++) acc[u][v]=0.f;
  int ln = tid >> 1;
  int lq = tid & 1;
  const float* arow = base + (size_t)b*bstride + (size_t)(n0+ln)*FF + lq*16;
  bool valid = (n0+ln) < NN;
  for(int kc=0;kc<4;kc++){
    __syncthreads();
    const float4* Wg4 = (const float4*)(Wg + kc*32*KD);
    #pragma unroll
    for(int u=0;u<4;u++){
      int idx = tid + u*256;
      float4 v = Wg4[idx];
      *(float4*)&Wsh[idx>>5][(idx&31)*4] = v;
    }
    #pragma unroll
    for(int u=0;u<4;u++){
      int ko = lq*16 + u*4;
      float4 v = valid ? *(const float4*)(arow + kc*32 + u*4)
                       : make_float4(0.f,0.f,0.f,0.f);
      Ash[ko][ln]=v.x; Ash[ko+1][ln]=v.y; Ash[ko+2][ln]=v.z; Ash[ko+3][ln]=v.w;
    }
    __syncthreads();
    #pragma unroll
    for(int kk=0;kk<32;kk++){
      float4 w0 = *(float4*)&Wsh[kk][jb];
      float4 w1 = *(float4*)&Wsh[kk][jb+4];
      float4 a0 = *(float4*)&Ash[kk][nb];
      float4 a1 = *(float4*)&Ash[kk][nb+4];
      float aa[8] = {a0.x,a0.y,a0.z,a0.w,a1.x,a1.y,a1.z,a1.w};
      float ww[8] = {w0.x,w0.y,w0.z,w0.w,w1.x,w1.y,w1.z,w1.w};
      #pragma unroll
      for(int u=0;u<8;u++)
        #pragma unroll
        for(int v=0;v<8;v++) acc[u][v] += aa[u]*ww[v];
    }
  }
  #pragma unroll
  for(int u=0;u<8;u++){
    int row = n0 + nb + u;
    if(row < NN){
      float* dst = &g_obuf[((size_t)b*NN+row)*KD + jb];
      *(float4*)dst     = make_float4(acc[u][0],acc[u][1],acc[u][2],acc[u][3]);
      *(float4*)(dst+4) = make_float4(acc[u][4],acc[u][5],acc[u][6],acc[u][7]);
    }
  }
}

// CSR gather + bias + relu; optionally fused next-layer scores
__global__ void k_agg(int c, const float* __restrict__ bias, float* __restrict__ out,
                      const float* __restrict__ pnext){
  int gw = (blockIdx.x*blockDim.x + threadIdx.x) >> 5;
  int lane = threadIdx.x & 31;
  if(gw >= BN*NN) return;
  int b = gw / NN, v = gw - b*NN;
  int beg = g_colptr[v], end = g_colptr[v+1];
  const float* ob = g_obuf + (size_t)b*NN*KD + lane*4;
  float ax=0.f, ay=0.f, az=0.f, aw=0.f;
  int j = beg;
  for(; j+7 < end; j+=8){
    int   rr[8]; float wv[8]; float4 o[8];
    #pragma unroll
    for(int u=0;u<8;u++){ rr[u]=g_erow[j+u]; wv[u]=g_ewn[j+u]; }
    #pragma unroll
    for(int u=0;u<8;u++) o[u] = *(const float4*)(ob + (size_t)rr[u]*KD);
    #pragma unroll
    for(int u=0;u<8;u++){
      ax += wv[u]*o[u].x; ay += wv[u]*o[u].y;
      az += wv[u]*o[u].z; aw += wv[u]*o[u].w;
    }
  }
  for(; j<end; j++){
    int r0=g_erow[j]; float w0=g_ewn[j];
    float4 o0=*(const float4*)(ob + (size_t)r0*KD);
    ax += w0*o0.x; ay += w0*o0.y; az += w0*o0.z; aw += w0*o0.w;
  }
  float4 bv = *(const float4*)(bias + c*KD + lane*4);
  float4 res;
  res.x = fmaxf(ax+bv.x, 0.f);
  res.y = fmaxf(ay+bv.y, 0.f);
  res.z = fmaxf(az+bv.z, 0.f);
  res.w = fmaxf(aw+bv.w, 0.f);
  float* dst = out ? out : g_buf1;
  *(float4*)(dst + ((size_t)b*NN + v)*KD + lane*4) = res;
  if(pnext){
    float4 pv = *(const float4*)(pnext + lane*4);
    float sc = res.x*pv.x + res.y*pv.y + res.z*pv.z + res.w*pv.w;
    #pragma unroll
    for(int o2=16;o2;o2>>=1) sc += __shfl_xor_sync(0xFFFFFFFFu, sc, o2);
    if(lane==0) g_scores[b*NN+v] = sc;
  }
}

extern "C" void kernel_launch(void* const* d_in, const int* in_sizes, int n_in,
                              void* d_out, int out_size){
  const float* x    = (const float*)d_in[0];
  const void*  ei   = d_in[1];
  const float* ew   = (const float*)d_in[2];
  const float* W0   = (const float*)d_in[3];
  const float* p    = (const float*)d_in[4];
  const float* wih  = (const float*)d_in[5];
  const float* whh  = (const float*)d_in[6];
  const float* bih  = (const float*)d_in[7];
  const float* bhh  = (const float*)d_in[8];
  const float* bias = (const float*)d_in[9];
  float* out = (float*)d_out;

  k_convert<<<(EE+255)/256,256>>>(ei);
  k_init<<<768,256>>>(W0, wih, whh);
  k_degcnt<<<(ENE+255)/256,256>>>(ew);
  k_dinv<<<(NN+255)/256,256>>>();
  k_scan<<<1,1024>>>();
  k_fill<<<(ENE+255)/256,256>>>(ew);

  const size_t xbs = (size_t)TT*NN*FF;
  const size_t bbs = (size_t)NN*FF;
  const int wgrid = (BN*NN*32+255)/256;
  for(int t=0;t<TT;t++){
    const float* xt = x + (size_t)t*NN*FF;
    // layer 0 (full pipeline every step)
    k_scores<<<wgrid,256>>>(xt, xbs, p, 0);
    k_topk<<<BN,1024>>>(xt, xbs, p, 0);
    k_gru<<<dim3(8,BN),384>>>(0, bih, bhh);
    k_gemm<<<dim3((NN+127)/128,BN),256>>>(xt, xbs, 0);
    k_agg<<<wgrid,256>>>(0, bias, nullptr, p + FF);  // fused layer-1 scores
    // layer 1: evolve W every step; GEMM+propagate only at final step
    k_topk<<<BN,1024>>>(nullptr, bbs, p, 1);
    k_gru<<<dim3(8,BN),384>>>(1, bih, bhh);
    if(t==TT-1){
      k_gemm<<<dim3((NN+127)/128,BN),256>>>(nullptr, bbs, 1);
      k_agg<<<wgrid,256>>>(1, bias, out, nullptr);
    }
  }
}

// round 12
// speedup vs baseline: 1.7868x; 1.6381x over previous
#include <cuda_runtime.h>
#include <math.h>
#include <stdint.h>

#define BN 2
#define TT 8
#define NN 10000
#define FF 128
#define EE 320000
#define ENE (EE+NN)
#define LL 2
#define KD 128
#define G3 384

__device__ int   g_src[EE];
__device__ int   g_tgt[EE];
__device__ float g_deg[NN];
__device__ float g_dinv[NN];
__device__ int   g_cnt[NN];
__device__ int   g_colptr[NN+1];
__device__ int   g_erow[ENE];
__device__ float g_ewn[ENE];
__device__ float g_W[BN*LL*FF*KD];        // [b][c][k(din)][i(dout)]
__device__ float g_buf1[BN*NN*KD];        // layer-0 output
__device__ float g_obuf[BN*NN*KD];        // GEMM result
__device__ float g_scores[LL*BN*NN];      // per-layer scores
__device__ float g_pooled[LL*BN*KD*FF];   // per-layer pooled [c][b][i][k]
__device__ float g_wT[LL*2*FF*G3];        // [c][m][k][j]

__global__ void k_convert(const void* __restrict__ ei){
  const long long* q = (const long long*)ei;
  bool is64 = true;
  #pragma unroll
  for(int j=0;j<8;j++){ long long v = q[j]; if(v < 0 || v >= NN) is64 = false; }
  int e = blockIdx.x*blockDim.x + threadIdx.x;
  if(e < EE){
    if(is64){ g_src[e] = (int)q[e]; g_tgt[e] = (int)q[EE+e]; }
    else { const int* pi = (const int*)ei; g_src[e] = pi[e]; g_tgt[e] = pi[EE+e]; }
  }
}

__global__ void k_init(const float* __restrict__ W0, const float* __restrict__ wih,
                       const float* __restrict__ whh){
  int i = blockIdx.x*blockDim.x + threadIdx.x;
  if(i < NN){ g_deg[i]=0.f; g_cnt[i]=0; }
  if(i < BN*LL*FF*KD){ g_W[i] = W0[i & (LL*FF*KD - 1)]; }
  if(i < LL*2*FF*G3){
    int j = i % G3; int t2 = i / G3; int k = t2 % FF; int t3 = t2 / FF;
    int m = t3 & 1; int cc = t3 >> 1;
    const float* src = m ? whh : wih;
    g_wT[i] = src[((size_t)cc*G3 + j)*FF + k];
  }
}

__global__ void k_degcnt(const float* __restrict__ ew){
  int e = blockIdx.x*blockDim.x + threadIdx.x;
  if(e >= ENE) return;
  int col; float w;
  if(e < EE){ col = g_tgt[e]; w = ew[e]; } else { col = e - EE; w = 1.f; }
  atomicAdd(&g_deg[col], w);
  atomicAdd(&g_cnt[col], 1);
}

__global__ void k_dinv(){
  int i = blockIdx.x*blockDim.x + threadIdx.x;
  if(i < NN){ float d = g_deg[i]; g_dinv[i] = d > 0.f ? rsqrtf(d) : 0.f; }
}

__global__ void k_scan(){
  __shared__ int part[1024];
  int tid = threadIdx.x;
  const int CH = 10;
  int base = tid*CH;
  int loc[CH]; int s = 0;
  #pragma unroll
  for(int i=0;i<CH;i++){ int idx = base+i; int v = (idx<NN)?g_cnt[idx]:0; loc[i]=s; s+=v; }
  part[tid]=s; __syncthreads();
  for(int off=1; off<1024; off<<=1){
    int v = part[tid];
    int add = (tid>=off)? part[tid-off] : 0;
    __syncthreads();
    part[tid] = v+add;
    __syncthreads();
  }
  int excl = (tid>0)? part[tid-1] : 0;
  #pragma unroll
  for(int i=0;i<CH;i++){ int idx = base+i; if(idx<NN) g_colptr[idx]=excl+loc[i]; }
  if(tid==1023) g_colptr[NN]=part[1023];
  for(int idx=tid; idx<NN; idx+=1024) g_cnt[idx]=0;
}

__global__ void k_fill(const float* __restrict__ ew){
  int e = blockIdx.x*blockDim.x + threadIdx.x;
  if(e >= ENE) return;
  int col, r; float w;
  if(e < EE){ col = g_tgt[e]; r = g_src[e]; w = ew[e]; }
  else { col = e - EE; r = col; w = 1.f; }
  int pos = g_colptr[col] + atomicAdd(&g_cnt[col], 1);
  g_erow[pos] = r;
  g_ewn[pos] = g_dinv[r]*w*g_dinv[col];
}

// scores for layer 0 (reads x_t)
__global__ void k_scores(const float* __restrict__ in, size_t bstride,
                         const float* __restrict__ p, int c){
  int gw = (blockIdx.x*blockDim.x + threadIdx.x) >> 5;
  int lane = threadIdx.x & 31;
  if(gw >= BN*NN) return;
  int b = gw / NN, n = gw - b*NN;
  const float4* row = (const float4*)(in + (size_t)b*bstride + (size_t)n*FF);
  float4 xv = row[lane];
  float4 pv = ((const float4*)(p + c*FF))[lane];
  float acc = xv.x*pv.x + xv.y*pv.y + xv.z*pv.z + xv.w*pv.w;
  #pragma unroll
  for(int o=16;o;o>>=1) acc += __shfl_xor_sync(0xFFFFFFFFu, acc, o);
  if(lane==0) g_scores[(size_t)c*BN*NN + b*NN + n]=acc;
}

__global__ void k_topk(const float* __restrict__ in, size_t bstride,
                       const float* __restrict__ p, int c){
  __shared__ unsigned skey[NN];
  __shared__ int hist[256];
  __shared__ unsigned long long cand[256];
  __shared__ int sidx[128];
  __shared__ float sscale[128];
  __shared__ float s_pn;
  __shared__ unsigned s_pref;
  __shared__ int s_need, s_cnt;
  int tid = threadIdx.x, b = blockIdx.x;
  if(tid==0){ s_pn=0.f; s_cnt=0; s_need=128; s_pref=0; }
  __syncthreads();
  if(tid < FF){ float pv = p[c*FF+tid]; atomicAdd(&s_pn, pv*pv); }
  const float* sc_in = g_scores + (size_t)c*BN*NN + b*NN;
  for(int n=tid; n<NN; n+=1024){
    float s = sc_in[n];
    unsigned u = __float_as_uint(s);
    u ^= (u>>31) ? 0xFFFFFFFFu : 0x80000000u;
    skey[n] = u;
  }
  if(tid < 256) hist[tid]=0;
  __syncthreads();
  float pnorm = sqrtf(s_pn);
  for(int r=0;r<4;r++){
    int shift = 24-8*r;
    unsigned pref = s_pref;
    int need = s_need;
    for(int n=tid;n<NN;n+=1024){
      unsigned k = skey[n];
      bool ok = (r==0) || ((k >> (shift+8)) == pref);
      if(ok) atomicAdd(&hist[(k>>shift)&255],1);
    }
    __syncthreads();
    // warp 0: parallel suffix selection over descending buckets
    if(tid < 32){
      int vals[8], loc[8]; int s = 0;
      #pragma unroll
      for(int u=0;u<8;u++){ int v = hist[255-(tid*8+u)]; loc[u]=s; vals[u]=v; s+=v; }
      int t = s;
      #pragma unroll
      for(int off=1; off<32; off<<=1){
        int n3 = __shfl_up_sync(0xFFFFFFFFu, t, off);
        if(tid >= off) t += n3;
      }
      int lane_excl = t - s;
      #pragma unroll
      for(int u=0;u<8;u++){
        int excl = lane_excl + loc[u];
        int incl = excl + vals[u];
        if(excl < need && incl >= need){
          s_need = need - excl;
          s_pref = (pref<<8)|(unsigned)(255-(tid*8+u));
        }
      }
    }
    __syncthreads();
    if(r<3 && tid<256) hist[tid]=0;
    __syncthreads();
  }
  unsigned kth = s_pref;
  for(int i=tid;i<256;i+=1024) cand[i]=0xFFFFFFFFFFFFFFFFull;
  __syncthreads();
  for(int n=tid;n<NN;n+=1024){
    unsigned k = skey[n];
    if(k >= kth){
      int pos = atomicAdd(&s_cnt,1);
      if(pos < 256){
        unsigned long long comp = ((unsigned long long)k<<32) | (unsigned)(~n);
        cand[pos] = ~comp;   // ascending sort of ~comp == descending (key, idx-asc)
      }
    }
  }
  __syncthreads();
  for(int kk=2; kk<=256; kk<<=1){
    for(int j=kk>>1; j>0; j>>=1){
      if(tid < 256){
        int ixj = tid ^ j;
        if(ixj > tid){
          bool up = ((tid & kk) == 0);
          unsigned long long a = cand[tid], b2 = cand[ixj];
          if((a > b2) == up){ cand[tid]=b2; cand[ixj]=a; }
        }
      }
      __syncthreads();
    }
  }
  if(tid < 128){
    unsigned long long comp = ~cand[tid];
    unsigned k = (unsigned)(comp>>32);
    int idx = (int)(~(unsigned)comp);
    unsigned u = (k & 0x80000000u) ? (k ^ 0x80000000u) : ~k;
    float val = __uint_as_float(u) / pnorm;
    sidx[tid] = idx;
    sscale[tid] = tanhf(val);
  }
  __syncthreads();
  const float* base = in ? in : g_buf1;
  float* pd = g_pooled + (size_t)(c*BN+b)*KD*FF;
  for(int e2=tid; e2<KD*FF; e2+=1024){
    int i = e2 >> 7, d = e2 & 127;
    pd[(size_t)i*FF+d] =
        base[(size_t)b*bstride + (size_t)sidx[i]*FF + d]*sscale[i];
  }
}

// fused GRU: both gate GEMMs + gating + W update in one kernel
__global__ void k_gru(int c, const float* __restrict__ bih, const float* __restrict__ bhh){
  __shared__ float sa0[FF][16];     // pooled slice [k][ii]
  __shared__ float sa1[FF][16];     // W slice     [k][ii]
  __shared__ float sg[16][G3];      // j<256: gi+gh ; j>=256: gin
  __shared__ float sghn[16][128];   // ghn
  int b = blockIdx.y;
  int i0 = blockIdx.x*16;
  int tid = threadIdx.x;            // 384
  const float* pp = g_pooled + (size_t)(c*BN+b)*KD*FF;
  for(int idx=tid; idx<16*FF; idx+=384){
    int ii = idx & 15, k = idx >> 4;
    sa0[k][ii] = pp[(size_t)(i0+ii)*FF + k];
    sa1[k][ii] = g_W[(((size_t)b*LL + c)*FF + k)*KD + (i0+ii)];
  }
  __syncthreads();
  int j = tid;
  const float* w0row = &g_wT[(size_t)(c*2+0)*FF*G3 + j];
  const float* w1row = &g_wT[(size_t)(c*2+1)*FF*G3 + j];
  float acc0[16], acc1[16];
  #pragma unroll
  for(int ii=0;ii<16;ii++){ acc0[ii]=0.f; acc1[ii]=0.f; }
  #pragma unroll 4
  for(int k=0;k<FF;k++){
    float w0 = w0row[(size_t)k*G3];
    float w1 = w1row[(size_t)k*G3];
    const float4* s0 = (const float4*)&sa0[k][0];
    const float4* s1 = (const float4*)&sa1[k][0];
    #pragma unroll
    for(int q=0;q<4;q++){
      float4 a = s0[q]; float4 h = s1[q];
      acc0[q*4+0]+=a.x*w0; acc0[q*4+1]+=a.y*w0; acc0[q*4+2]+=a.z*w0; acc0[q*4+3]+=a.w*w0;
      acc1[q*4+0]+=h.x*w1; acc1[q*4+1]+=h.y*w1; acc1[q*4+2]+=h.z*w1; acc1[q*4+3]+=h.w*w1;
    }
  }
  float bi = bih[c*G3+j], bh = bhh[c*G3+j];
  if(j < 256){
    #pragma unroll
    for(int ii=0;ii<16;ii++) sg[ii][j] = acc0[ii]+bi + acc1[ii]+bh;
  } else {
    #pragma unroll
    for(int ii=0;ii<16;ii++){ sg[ii][j] = acc0[ii]+bi; sghn[ii][j-256] = acc1[ii]+bh; }
  }
  __syncthreads();
  for(int idx=tid; idx<16*128; idx+=384){
    int ii = idx >> 7, jj = idx & 127;
    float r = 1.f/(1.f+expf(-sg[ii][jj]));
    float z = 1.f/(1.f+expf(-sg[ii][jj+128]));
    float n2 = tanhf(sg[ii][jj+256] + r*sghn[ii][jj]);
    float h = sa1[jj][ii];
    g_W[(((size_t)b*LL+c)*FF + jj)*KD + (i0+ii)] = (1.f-z)*n2 + z*h;
  }
}

// 128x128 tile GEMM, 8x8 micro-tile
__global__ void k_gemm(const float* __restrict__ in, size_t bstride, int c){
  __shared__ float Ash[32][132];
  __shared__ float Wsh[32][128];
  int b = blockIdx.y;
  int n0 = blockIdx.x*128;
  int tid = threadIdx.x;              // 256
  const float* base = in ? in : g_buf1;
  const float* Wg = &g_W[(size_t)(b*LL+c)*FF*KD];
  int tx = tid & 15, ty = tid >> 4;
  int jb = tx*8, nb = ty*8;
  float acc[8][8];
  #pragma unroll
  for(int u=0;u<8;u++)
    #pragma unroll
    for(int v=0;v<8;v++) acc[u][v]=0.f;
  int ln = tid >> 1;
  int lq = tid & 1;
  const float* arow = base + (size_t)b*bstride + (size_t)(n0+ln)*FF + lq*16;
  bool valid = (n0+ln) < NN;
  for(int kc=0;kc<4;kc++){
    __syncthreads();
    const float4* Wg4 = (const float4*)(Wg + kc*32*KD);
    #pragma unroll
    for(int u=0;u<4;u++){
      int idx = tid + u*256;
      float4 v = Wg4[idx];
      *(float4*)&Wsh[idx>>5][(idx&31)*4] = v;
    }
    #pragma unroll
    for(int u=0;u<4;u++){
      int ko = lq*16 + u*4;
      float4 v = valid ? *(const float4*)(arow + kc*32 + u*4)
                       : make_float4(0.f,0.f,0.f,0.f);
      Ash[ko][ln]=v.x; Ash[ko+1][ln]=v.y; Ash[ko+2][ln]=v.z; Ash[ko+3][ln]=v.w;
    }
    __syncthreads();
    #pragma unroll
    for(int kk=0;kk<32;kk++){
      float4 w0 = *(float4*)&Wsh[kk][jb];
      float4 w1 = *(float4*)&Wsh[kk][jb+4];
      float4 a0 = *(float4*)&Ash[kk][nb];
      float4 a1 = *(float4*)&Ash[kk][nb+4];
      float aa[8] = {a0.x,a0.y,a0.z,a0.w,a1.x,a1.y,a1.z,a1.w};
      float ww[8] = {w0.x,w0.y,w0.z,w0.w,w1.x,w1.y,w1.z,w1.w};
      #pragma unroll
      for(int u=0;u<8;u++)
        #pragma unroll
        for(int v=0;v<8;v++) acc[u][v] += aa[u]*ww[v];
    }
  }
  #pragma unroll
  for(int u=0;u<8;u++){
    int row = n0 + nb + u;
    if(row < NN){
      float* dst = &g_obuf[((size_t)b*NN+row)*KD + jb];
      *(float4*)dst     = make_float4(acc[u][0],acc[u][1],acc[u][2],acc[u][3]);
      *(float4*)(dst+4) = make_float4(acc[u][4],acc[u][5],acc[u][6],acc[u][7]);
    }
  }
}

// CSR gather + bias + relu; optionally fused next-layer scores
__global__ void k_agg(int c, const float* __restrict__ bias, float* __restrict__ out,
                      const float* __restrict__ pnext){
  int gw = (blockIdx.x*blockDim.x + threadIdx.x) >> 5;
  int lane = threadIdx.x & 31;
  if(gw >= BN*NN) return;
  int b = gw / NN, v = gw - b*NN;
  int beg = g_colptr[v], end = g_colptr[v+1];
  const float* ob = g_obuf + (size_t)b*NN*KD + lane*4;
  float ax=0.f, ay=0.f, az=0.f, aw=0.f;
  int j = beg;
  for(; j+7 < end; j+=8){
    int   rr[8]; float wv[8]; float4 o[8];
    #pragma unroll
    for(int u=0;u<8;u++){ rr[u]=g_erow[j+u]; wv[u]=g_ewn[j+u]; }
    #pragma unroll
    for(int u=0;u<8;u++) o[u] = *(const float4*)(ob + (size_t)rr[u]*KD);
    #pragma unroll
    for(int u=0;u<8;u++){
      ax += wv[u]*o[u].x; ay += wv[u]*o[u].y;
      az += wv[u]*o[u].z; aw += wv[u]*o[u].w;
    }
  }
  for(; j<end; j++){
    int r0=g_erow[j]; float w0=g_ewn[j];
    float4 o0=*(const float4*)(ob + (size_t)r0*KD);
    ax += w0*o0.x; ay += w0*o0.y; az += w0*o0.z; aw += w0*o0.w;
  }
  float4 bv = *(const float4*)(bias + c*KD + lane*4);
  float4 res;
  res.x = fmaxf(ax+bv.x, 0.f);
  res.y = fmaxf(ay+bv.y, 0.f);
  res.z = fmaxf(az+bv.z, 0.f);
  res.w = fmaxf(aw+bv.w, 0.f);
  float* dst = out ? out : g_buf1;
  *(float4*)(dst + ((size_t)b*NN + v)*KD + lane*4) = res;
  if(pnext){
    float4 pv = *(const float4*)(pnext + lane*4);
    float sc = res.x*pv.x + res.y*pv.y + res.z*pv.z + res.w*pv.w;
    #pragma unroll
    for(int o2=16;o2;o2>>=1) sc += __shfl_xor_sync(0xFFFFFFFFu, sc, o2);
    if(lane==0) g_scores[(size_t)1*BN*NN + b*NN + v] = sc;
  }
}

extern "C" void kernel_launch(void* const* d_in, const int* in_sizes, int n_in,
                              void* d_out, int out_size){
  const float* x    = (const float*)d_in[0];
  const void*  ei   = d_in[1];
  const float* ew   = (const float*)d_in[2];
  const float* W0   = (const float*)d_in[3];
  const float* p    = (const float*)d_in[4];
  const float* wih  = (const float*)d_in[5];
  const float* whh  = (const float*)d_in[6];
  const float* bih  = (const float*)d_in[7];
  const float* bhh  = (const float*)d_in[8];
  const float* bias = (const float*)d_in[9];
  float* out = (float*)d_out;

  // one-time stream/event creation (host resources only; no device memory)
  static cudaStream_t s1 = nullptr, s2 = nullptr;
  static cudaEvent_t eFork, eW1;
  static cudaEvent_t eT0[TT], eR0[TT], eA0[TT], eK1[TT];
  if(!s1){
    cudaStreamCreateWithFlags(&s1, cudaStreamNonBlocking);
    cudaStreamCreateWithFlags(&s2, cudaStreamNonBlocking);
    cudaEventCreateWithFlags(&eFork, cudaEventDisableTiming);
    cudaEventCreateWithFlags(&eW1,  cudaEventDisableTiming);
    for(int t=0;t<TT;t++){
      cudaEventCreateWithFlags(&eT0[t], cudaEventDisableTiming);
      cudaEventCreateWithFlags(&eR0[t], cudaEventDisableTiming);
      cudaEventCreateWithFlags(&eA0[t], cudaEventDisableTiming);
      cudaEventCreateWithFlags(&eK1[t], cudaEventDisableTiming);
    }
  }

  const size_t xbs = (size_t)TT*NN*FF;
  const size_t bbs = (size_t)NN*FF;
  const int wgrid = (BN*NN*32+255)/256;

  // fork s1 from capture stream, prefetch t=0 layer-0 scores+topk
  cudaEventRecord(eFork, 0);
  cudaStreamWaitEvent(s1, eFork, 0);
  k_scores<<<wgrid,256,0,s1>>>(x, xbs, p, 0);
  k_topk<<<BN,1024,0,s1>>>(x, xbs, p, 0);
  cudaEventRecord(eT0[0], s1);

  // precompute on main stream (overlaps with s1)
  k_convert<<<(EE+255)/256,256>>>(ei);
  k_init<<<768,256>>>(W0, wih, whh);
  k_degcnt<<<(ENE+255)/256,256>>>(ew);
  k_dinv<<<(NN+255)/256,256>>>();
  k_scan<<<1,1024>>>();
  k_fill<<<(ENE+255)/256,256>>>(ew);

  for(int t=0;t<TT;t++){
    const float* xt = x + (size_t)t*NN*FF;
    // main chain: gru0 -> gemm0 -> agg0
    cudaStreamWaitEvent(0, eT0[t], 0);
    k_gru<<<dim3(8,BN),384>>>(0, bih, bhh);
    cudaEventRecord(eR0[t], 0);
    // prefetch next step's layer-0 scores+topk on s1 (pooled0 WAR via eR0)
    if(t+1 < TT){
      const float* xn = x + (size_t)(t+1)*NN*FF;
      cudaStreamWaitEvent(s1, eR0[t], 0);
      k_scores<<<wgrid,256,0,s1>>>(xn, xbs, p, 0);
      k_topk<<<BN,1024,0,s1>>>(xn, xbs, p, 0);
      cudaEventRecord(eT0[t+1], s1);
    }
    k_gemm<<<dim3((NN+127)/128,BN),256>>>(xt, xbs, 0);
    if(t > 0) cudaStreamWaitEvent(0, eK1[t-1], 0);   // buf1/scores1 WAR vs topk1(t-1)
    k_agg<<<wgrid,256>>>(0, bias, nullptr, p + FF);  // fused layer-1 scores
    cudaEventRecord(eA0[t], 0);
    // side chain: layer-1 evolve on s2
    cudaStreamWaitEvent(s2, eA0[t], 0);
    k_topk<<<BN,1024,0,s2>>>(nullptr, bbs, p, 1);
    cudaEventRecord(eK1[t], s2);
    k_gru<<<dim3(8,BN),384,0,s2>>>(1, bih, bhh);
    if(t == TT-1) cudaEventRecord(eW1, s2);
  }
  // tail: layer-1 GEMM + propagate (joins s2; s1 already joined via eT0[7])
  cudaStreamWaitEvent(0, eW1, 0);
  k_gemm<<<dim3((NN+127)/128,BN),256>>>(nullptr, bbs, 1);
  k_agg<<<wgrid,256>>>(1, bias, out, nullptr);
}